// round 14
// baseline (speedup 1.0000x reference)
#include <cuda_runtime.h>
#include <cuda_fp16.h>

#define NN 14      // nodes per graph
#define NH 4       // heads
#define NC 64      // per-head channels
#define NO 256     // NH*NC
#define FIN 128
#define NEG 0.2f
#define MAXE 200   // >= E + NN = 196
#define XSTH 136   // xh/x2h row stride (halves)
#define HST 264    // hsm row stride (halves)
#define MST 24     // Msm row stride (halves)
#define PST 72     // part row stride (floats)

typedef unsigned int uint;

__device__ __forceinline__ uint smaddr(const void* p) {
    return (uint)__cvta_generic_to_shared(p);
}
__device__ __forceinline__ void ldsm4(uint& r0, uint& r1, uint& r2, uint& r3, uint a) {
    asm volatile("ldmatrix.sync.aligned.m8n8.x4.shared.b16 {%0,%1,%2,%3},[%4];"
        : "=r"(r0), "=r"(r1), "=r"(r2), "=r"(r3) : "r"(a));
}
__device__ __forceinline__ void ldsm4t(uint& r0, uint& r1, uint& r2, uint& r3, uint a) {
    asm volatile("ldmatrix.sync.aligned.m8n8.x4.trans.shared.b16 {%0,%1,%2,%3},[%4];"
        : "=r"(r0), "=r"(r1), "=r"(r2), "=r"(r3) : "r"(a));
}
// D(16x8,f32) += A(16x16,f16) @ B(16x8,f16)
__device__ __forceinline__ void mma_f16(float4& d, uint a0, uint a1, uint a2, uint a3,
                                        uint b0, uint b1) {
    asm("mma.sync.aligned.m16n8k16.row.col.f32.f16.f16.f32 "
        "{%0,%1,%2,%3}, {%4,%5,%6,%7}, {%8,%9}, {%0,%1,%2,%3};"
        : "+f"(d.x), "+f"(d.y), "+f"(d.z), "+f"(d.w)
        : "r"(a0), "r"(a1), "r"(a2), "r"(a3), "r"(b0), "r"(b1));
}

// ---- precomputed weights (fragment-major fp16, same layout as round 13) ----
__device__ uint2 g_W1h[8 * 32 * 32];
__device__ uint2 g_W2h[4 * 32 * 32];
__device__ float4 g_af1[32 * 32];
__device__ float4 g_af2[32 * 32];
__device__ float  g_wfused[NN * NC];   // W_lin @ W_pred
__device__ float  g_bfused;
__device__ int    g_is64;

__global__ void prep_kernel(const float* __restrict__ W1, const float* __restrict__ as1,
                            const float* __restrict__ ad1,
                            const float* __restrict__ W2, const float* __restrict__ as2,
                            const float* __restrict__ ad2,
                            const float* __restrict__ Wlin, const float* __restrict__ blin,
                            const float* __restrict__ Wpred, const float* __restrict__ bpred,
                            const int* __restrict__ edges)
{
    int tid = blockIdx.x * blockDim.x + threadIdx.x;
    int nt  = gridDim.x * blockDim.x;

    for (int i = tid; i < 8*32*32; i += nt) {
        int kt = i >> 10, r = i & 1023, ntile = r >> 5, lane = r & 31;
        int q = lane & 3, n = ntile*8 + (lane >> 2);
        int k0 = kt*16 + 2*q;
        __half2 b0 = __halves2half2(__float2half_rn(W1[k0*NO + n]),
                                    __float2half_rn(W1[(k0+1)*NO + n]));
        __half2 b1 = __halves2half2(__float2half_rn(W1[(k0+8)*NO + n]),
                                    __float2half_rn(W1[(k0+9)*NO + n]));
        g_W1h[i] = make_uint2(*(uint*)&b0, *(uint*)&b1);
    }
    for (int i = tid; i < 4*32*32; i += nt) {
        int kt = i >> 10, r = i & 1023, ntile = r >> 5, lane = r & 31;
        int q = lane & 3, n = ntile*8 + (lane >> 2);
        int k0 = kt*16 + 2*q;
        __half2 b0 = __halves2half2(__float2half_rn(W2[k0*NO + n]),
                                    __float2half_rn(W2[(k0+1)*NO + n]));
        __half2 b1 = __halves2half2(__float2half_rn(W2[(k0+8)*NO + n]),
                                    __float2half_rn(W2[(k0+9)*NO + n]));
        g_W2h[i] = make_uint2(*(uint*)&b0, *(uint*)&b1);
    }
    for (int i = tid; i < 32*32; i += nt) {
        int j = i >> 5, lane = i & 31;
        int half_ = j >> 4, ntile = j & 15;
        int h = 2*half_ + (ntile >> 3);
        int c = (ntile & 7)*8 + 2*(lane & 3);
        g_af1[i] = make_float4(as1[h*NC + c], as1[h*NC + c + 1],
                               ad1[h*NC + c], ad1[h*NC + c + 1]);
        g_af2[i] = make_float4(as2[h*NC + c], as2[h*NC + c + 1],
                               ad2[h*NC + c], ad2[h*NC + c + 1]);
    }
    for (int i = tid; i < NN * NC; i += nt) {
        float s = 0.f;
        #pragma unroll
        for (int j = 0; j < NC/2; j++) s = fmaf(Wlin[i*(NC/2) + j], Wpred[j], s);
        g_wfused[i] = s;
    }
    if (tid == 0) {
        float s = bpred[0];
        #pragma unroll
        for (int j = 0; j < NC/2; j++) s = fmaf(blin[j], Wpred[j], s);
        g_bfused = s;
        int any = 0;
        #pragma unroll
        for (int k = 1; k < 256; k += 2) any |= edges[k];
        g_is64 = (any == 0) ? 1 : 0;
    }
}

// One GAT layer for one graph; 4-warp CTA, warp w owns head w (cols 64w..64w+63).
// xa: fp16 [16][XSTH]. xout: fp16 [16][XSTH] (may alias xa — the syncthreads
// before head-mean guarantees all GEMM reads finished). Aggregation runs as an
// fp16 mma with A = attention matrix M, B = h (both warp-private in smem).
template<int KT, bool RELU>
__device__ __forceinline__ void gat_layer(
    const uint2* __restrict__ Wh, const float4* __restrict__ af,
    const float* __restrict__ bias,
    const __half* xa, __half* xout,
    __half* hsm, __half* Msm, float* part, float* alj,
    const unsigned char* srcS, const int* off,
    int t, int lane, int w)
{
    const int r = lane >> 2, q = lane & 3;

    // ---- GEMM: D[nt] = x(16xK) @ W(Kx8), 8 n-tiles (head w) ----
    float4 D[8];
    #pragma unroll
    for (int nt = 0; nt < 8; nt++) D[nt] = make_float4(0.f, 0.f, 0.f, 0.f);

    const uint xaddr = smaddr(xa) + ((lane & 15) * XSTH + (lane >> 4) * 8) * 2;
    const uint2* wp = Wh + w*256 + lane;
    #pragma unroll
    for (int kt = 0; kt < KT; kt++) {
        uint a0, a1, a2, a3;
        ldsm4(a0, a1, a2, a3, xaddr + kt*32);
        #pragma unroll
        for (int nt = 0; nt < 8; nt++) {
            uint2 b = wp[kt*1024 + nt*32];
            mma_f16(D[nt], a0, a1, a2, a3, b.x, b.y);
        }
    }

    // ---- attention logits for head w (from D fragments) ----
    {
        float s0 = 0.f, s1 = 0.f, d0 = 0.f, d1 = 0.f;
        const float4* afp = af + w*256 + lane;
        #pragma unroll
        for (int nt = 0; nt < 8; nt++) {
            float4 A = afp[nt*32];
            s0 = fmaf(D[nt].x, A.x, fmaf(D[nt].y, A.y, s0));
            s1 = fmaf(D[nt].z, A.x, fmaf(D[nt].w, A.y, s1));
            d0 = fmaf(D[nt].x, A.z, fmaf(D[nt].y, A.w, d0));
            d1 = fmaf(D[nt].z, A.z, fmaf(D[nt].w, A.w, d1));
        }
        #pragma unroll
        for (int o = 1; o < 4; o <<= 1) {
            s0 += __shfl_xor_sync(0xffffffffu, s0, o);
            s1 += __shfl_xor_sync(0xffffffffu, s1, o);
            d0 += __shfl_xor_sync(0xffffffffu, d0, o);
            d1 += __shfl_xor_sync(0xffffffffu, d1, o);
        }
        if (q == 0) {
            alj[r*8 + w]     = s0;
            alj[r*8 + 4 + w] = d0;
            if (r < 6) {
                alj[(r+8)*8 + w]     = s1;
                alj[(r+8)*8 + 4 + w] = d1;
            }
        }
    }
    __syncwarp();

    // ---- M-build (warp-private head): fp16 M in [16][MST], rows/cols >13 zero ----
    {
        __half2* Mr = (__half2*)(Msm + w*16*MST + lane*MST);
        if (lane < NN) {
            float md[NN];
            #pragma unroll
            for (int s = 0; s < NN; s++) md[s] = 0.f;
            float ad = alj[lane*8 + 4 + w];
            float dn = 0.f;
            int e1 = off[lane+1];
            for (int e = off[lane]; e < e1; e++) {
                int s = srcS[e];
                float v = alj[s*8 + w] + ad;
                v = (v > 0.f) ? v : NEG * v;
                float ex = __expf(v);
                md[s] += ex;
                dn += ex;
            }
            float inv = __fdividef(1.f, dn);
            #pragma unroll
            for (int j = 0; j < 7; j++)
                Mr[j] = __halves2half2(__float2half_rn(md[2*j]*inv),
                                       __float2half_rn(md[2*j+1]*inv));
            Mr[7] = __halves2half2(__float2half_rn(0.f), __float2half_rn(0.f));
        } else if (lane < 16) {
            #pragma unroll
            for (int j = 0; j < 8; j++)
                Mr[j] = __halves2half2(__float2half_rn(0.f), __float2half_rn(0.f));
        }
    }

    // ---- stage h (fp16) into warp-private column slice of hsm ----
    {
        #pragma unroll
        for (int nt = 0; nt < 8; nt++) {
            int c0 = w*64 + nt*8 + 2*q;
            __half2 lo = __halves2half2(__float2half_rn(D[nt].x), __float2half_rn(D[nt].y));
            __half2 hi = __halves2half2(__float2half_rn(D[nt].z), __float2half_rn(D[nt].w));
            *(__half2*)&hsm[r*HST + c0]     = lo;
            *(__half2*)&hsm[(r+8)*HST + c0] = hi;
        }
    }
    __syncwarp();

    // ---- aggregation via mma: D2 = M(16x16) @ h(16x64) ----
    float4 D2[8];
    #pragma unroll
    for (int nt = 0; nt < 8; nt++) D2[nt] = make_float4(0.f, 0.f, 0.f, 0.f);
    {
        uint ma0, ma1, ma2, ma3;
        uint maddr = smaddr(Msm) + (w*16*MST + (lane & 15)*MST + (lane >> 4)*8) * 2;
        ldsm4(ma0, ma1, ma2, ma3, maddr);
        const uint hrow = ((lane & 7) + ((lane >> 3) & 1) * 8) * HST;
        #pragma unroll
        for (int p2 = 0; p2 < 4; p2++) {
            uint b00, b01, b10, b11;
            uint haddr = smaddr(hsm) + (hrow + w*64 + p2*16 + (lane >> 4)*8) * 2;
            ldsm4t(b00, b01, b10, b11, haddr);
            mma_f16(D2[2*p2],   ma0, ma1, ma2, ma3, b00, b01);
            mma_f16(D2[2*p2+1], ma0, ma1, ma2, ma3, b10, b11);
        }
    }

    // ---- store per-head partials (f32) ----
    {
        float* pb = part + w*16*PST;
        #pragma unroll
        for (int nt = 0; nt < 8; nt++) {
            int c0 = nt*8 + 2*q;
            *(float2*)&pb[r*PST + c0]     = make_float2(D2[nt].x, D2[nt].y);
            *(float2*)&pb[(r+8)*PST + c0] = make_float2(D2[nt].z, D2[nt].w);
        }
    }
    __syncthreads();   // all heads' partials ready (also: all GEMM xa reads done)

    // ---- head mean + bias (+relu) -> xout fp16; pad rows zeroed ----
    for (int i = t; i < NN*NC; i += 128) {
        int n = i >> 6, c = i & 63;
        float v = 0.25f * (part[n*PST + c]        + part[1152 + n*PST + c]
                         + part[2304 + n*PST + c] + part[3456 + n*PST + c]) + bias[c];
        if (RELU) v = fmaxf(v, 0.f);
        xout[n*XSTH + c] = __float2half_rn(v);
    }
    for (int i = t; i < 2*XSTH; i += 128) xout[NN*XSTH + i] = __float2half_rn(0.f);
    __syncthreads();   // xout ready
}

__global__ void __launch_bounds__(128, 5)
gat_kernel(const float* __restrict__ feature, const int* __restrict__ eraw,
           const float* __restrict__ b1v, const float* __restrict__ b2v,
           float* __restrict__ out, int E)
{
    __shared__ __align__(16) __half xh[16*XSTH];
    __shared__ __align__(16) __half x2h[16*XSTH];
    __shared__ __align__(16) __half hsm[16*HST];
    __shared__ __align__(16) __half Msm[4*16*MST];
    __shared__ __align__(16) float part[4*16*PST];
    __shared__ float alj[NN*8];
    __shared__ unsigned char srcS[MAXE];
    __shared__ int cnt[NN], off[NN+1];
    __shared__ float red[4];

    const int g = blockIdx.x;
    const int t = threadIdx.x;
    const int lane = t & 31, w = t >> 5;
    const int NE = E + NN;
    const int is64 = g_is64;

    if (w == 0) {
        // ---- warp 0: counting sort of edges by dst (self-loops appended) ----
        if (lane < NN) cnt[lane] = 0;
        __syncwarp();
        for (int e = lane; e < NE; e += 32) {
            int d;
            if (e < E) {
                size_t base = ((size_t)g * E + e) * 2;
                d = is64 ? (int)((const long long*)eraw)[base + 1] : eraw[base + 1];
            } else d = e - E;
            atomicAdd(&cnt[d], 1);
        }
        __syncwarp();
        if (lane == 0) {
            int s = 0;
            #pragma unroll
            for (int i = 0; i < NN; i++) { off[i] = s; s += cnt[i]; cnt[i] = off[i]; }
            off[NN] = s;
        }
        __syncwarp();
        for (int e = lane; e < NE; e += 32) {
            int s, d;
            if (e < E) {
                size_t base = ((size_t)g * E + e) * 2;
                if (is64) { const long long* p = (const long long*)eraw;
                            s = (int)p[base]; d = (int)p[base + 1]; }
                else      { s = eraw[base];   d = eraw[base + 1]; }
            } else { s = d = e - E; }
            int pos = atomicAdd(&cnt[d], 1);
            srcS[pos] = (unsigned char)s;
        }
    } else {
        // ---- warps 1-3: load features -> fp16 xh [16][XSTH]; zero pad rows ----
        const float4* xg = (const float4*)(feature + (size_t)g * NN * FIN);
        for (int i = t - 32; i < NN*32; i += 96) {
            int n = i >> 5, k4 = i & 31;
            float4 v = xg[i];
            __half2 lo = __halves2half2(__float2half_rn(v.x), __float2half_rn(v.y));
            __half2 hi = __halves2half2(__float2half_rn(v.z), __float2half_rn(v.w));
            *(uint2*)&xh[n*XSTH + k4*4] = make_uint2(*(uint*)&lo, *(uint*)&hi);
        }
        for (int i = t - 32; i < 2*XSTH; i += 96) xh[NN*XSTH + i] = __float2half_rn(0.f);
    }
    __syncthreads();

    gat_layer<8, true >(g_W1h, g_af1, b1v, xh,  x2h, hsm, Msm, part, alj,
                        srcS, off, t, lane, w);
    gat_layer<4, false>(g_W2h, g_af2, b2v, x2h, x2h, hsm, Msm, part, alj,
                        srcS, off, t, lane, w);

    // ---- fused head: sigmoid(flat . w_fused + b_fused) ----
    float p = 0.f;
    for (int i = t; i < NN*NC; i += 128) {
        int n = i >> 6, c = i & 63;
        p = fmaf(__half2float(x2h[n*XSTH + c]), g_wfused[i], p);
    }
    #pragma unroll
    for (int o = 16; o; o >>= 1) p += __shfl_xor_sync(0xffffffffu, p, o);
    if (lane == 0) red[w] = p;
    __syncthreads();
    if (t == 0) {
        float s = g_bfused + (red[0] + red[1]) + (red[2] + red[3]);
        out[g] = 1.f / (1.f + __expf(-s));
    }
}

extern "C" void kernel_launch(void* const* d_in, const int* in_sizes, int n_in,
                              void* d_out, int out_size)
{
    const float* feature = (const float*)d_in[0];
    const int*   edges   = (const int*)  d_in[1];
    const float* W1   = (const float*)d_in[2];
    const float* as1  = (const float*)d_in[3];
    const float* ad1  = (const float*)d_in[4];
    const float* b1   = (const float*)d_in[5];
    const float* W2   = (const float*)d_in[6];
    const float* as2  = (const float*)d_in[7];
    const float* ad2  = (const float*)d_in[8];
    const float* b2   = (const float*)d_in[9];
    const float* Wlin = (const float*)d_in[10];
    const float* blin = (const float*)d_in[11];
    const float* Wpred= (const float*)d_in[12];
    const float* bpred= (const float*)d_in[13];

    int B = in_sizes[0] / (NN * FIN);       // 16384
    int E = in_sizes[1] / (2 * B);          // 182

    prep_kernel<<<48, 256>>>(W1, as1, ad1, W2, as2, ad2,
                             Wlin, blin, Wpred, bpred, edges);
    gat_kernel<<<B, 128>>>(feature, edges, b1, b2, (float*)d_out, E);
}

// round 15
// speedup vs baseline: 1.2730x; 1.2730x over previous
#include <cuda_runtime.h>
#include <cuda_fp16.h>

#define NN 14      // nodes per graph
#define NH 4       // heads
#define NC 64      // per-head channels
#define NO 256     // NH*NC
#define FIN 128
#define NEG 0.2f
#define MAXE 200   // >= E + NN = 196
#define XSTH 136   // xh/x2h row stride (halves)
#define HST 264    // hsm row stride (halves); float view stride 132
#define MST 24     // Msm row stride (halves)

typedef unsigned int uint;

__device__ __forceinline__ uint smaddr(const void* p) {
    return (uint)__cvta_generic_to_shared(p);
}
__device__ __forceinline__ void ldsm4(uint& r0, uint& r1, uint& r2, uint& r3, uint a) {
    asm volatile("ldmatrix.sync.aligned.m8n8.x4.shared.b16 {%0,%1,%2,%3},[%4];"
        : "=r"(r0), "=r"(r1), "=r"(r2), "=r"(r3) : "r"(a));
}
__device__ __forceinline__ void ldsm4t(uint& r0, uint& r1, uint& r2, uint& r3, uint a) {
    asm volatile("ldmatrix.sync.aligned.m8n8.x4.trans.shared.b16 {%0,%1,%2,%3},[%4];"
        : "=r"(r0), "=r"(r1), "=r"(r2), "=r"(r3) : "r"(a));
}
// D(16x8,f32) += A(16x16,f16) @ B(16x8,f16)
__device__ __forceinline__ void mma_f16(float4& d, uint a0, uint a1, uint a2, uint a3,
                                        uint b0, uint b1) {
    asm("mma.sync.aligned.m16n8k16.row.col.f32.f16.f16.f32 "
        "{%0,%1,%2,%3}, {%4,%5,%6,%7}, {%8,%9}, {%0,%1,%2,%3};"
        : "+f"(d.x), "+f"(d.y), "+f"(d.z), "+f"(d.w)
        : "r"(a0), "r"(a1), "r"(a2), "r"(a3), "r"(b0), "r"(b1));
}

// ---- precomputed weights (fragment-major fp16) ----
__device__ uint2 g_W1h[8 * 32 * 32];
__device__ uint2 g_W2h[4 * 32 * 32];
__device__ float4 g_af1[32 * 32];
__device__ float4 g_af2[32 * 32];
__device__ float  g_wfused[NN * NC];   // W_lin @ W_pred
__device__ float  g_bfused;
__device__ int    g_is64;

__global__ void prep_kernel(const float* __restrict__ W1, const float* __restrict__ as1,
                            const float* __restrict__ ad1,
                            const float* __restrict__ W2, const float* __restrict__ as2,
                            const float* __restrict__ ad2,
                            const float* __restrict__ Wlin, const float* __restrict__ blin,
                            const float* __restrict__ Wpred, const float* __restrict__ bpred,
                            const int* __restrict__ edges)
{
    int tid = blockIdx.x * blockDim.x + threadIdx.x;
    int nt  = gridDim.x * blockDim.x;

    for (int i = tid; i < 8*32*32; i += nt) {
        int kt = i >> 10, r = i & 1023, ntile = r >> 5, lane = r & 31;
        int q = lane & 3, n = ntile*8 + (lane >> 2);
        int k0 = kt*16 + 2*q;
        __half2 b0 = __halves2half2(__float2half_rn(W1[k0*NO + n]),
                                    __float2half_rn(W1[(k0+1)*NO + n]));
        __half2 b1 = __halves2half2(__float2half_rn(W1[(k0+8)*NO + n]),
                                    __float2half_rn(W1[(k0+9)*NO + n]));
        g_W1h[i] = make_uint2(*(uint*)&b0, *(uint*)&b1);
    }
    for (int i = tid; i < 4*32*32; i += nt) {
        int kt = i >> 10, r = i & 1023, ntile = r >> 5, lane = r & 31;
        int q = lane & 3, n = ntile*8 + (lane >> 2);
        int k0 = kt*16 + 2*q;
        __half2 b0 = __halves2half2(__float2half_rn(W2[k0*NO + n]),
                                    __float2half_rn(W2[(k0+1)*NO + n]));
        __half2 b1 = __halves2half2(__float2half_rn(W2[(k0+8)*NO + n]),
                                    __float2half_rn(W2[(k0+9)*NO + n]));
        g_W2h[i] = make_uint2(*(uint*)&b0, *(uint*)&b1);
    }
    for (int i = tid; i < 32*32; i += nt) {
        int j = i >> 5, lane = i & 31;
        int half_ = j >> 4, ntile = j & 15;
        int h = 2*half_ + (ntile >> 3);
        int c = (ntile & 7)*8 + 2*(lane & 3);
        g_af1[i] = make_float4(as1[h*NC + c], as1[h*NC + c + 1],
                               ad1[h*NC + c], ad1[h*NC + c + 1]);
        g_af2[i] = make_float4(as2[h*NC + c], as2[h*NC + c + 1],
                               ad2[h*NC + c], ad2[h*NC + c + 1]);
    }
    for (int i = tid; i < NN * NC; i += nt) {
        float s = 0.f;
        #pragma unroll
        for (int j = 0; j < NC/2; j++) s = fmaf(Wlin[i*(NC/2) + j], Wpred[j], s);
        g_wfused[i] = s;
    }
    if (tid == 0) {
        float s = bpred[0];
        #pragma unroll
        for (int j = 0; j < NC/2; j++) s = fmaf(blin[j], Wpred[j], s);
        g_bfused = s;
        int any = 0;
        #pragma unroll
        for (int k = 1; k < 256; k += 2) any |= edges[k];
        g_is64 = (any == 0) ? 1 : 0;
    }
}

// One GAT layer; 2-warp CTA, warp w owns cols 128w..128w+127 (heads 2w, 2w+1).
// xa/xout: fp16 [16][XSTH] (may alias). h staged fp16 into hsm slice, then the
// aggregation mma's head-pair sums are written back into the same slice as f32.
template<int KT, bool RELU>
__device__ __forceinline__ void gat_layer(
    const uint2* __restrict__ Wh, const float4* __restrict__ af,
    const float* __restrict__ bias,
    const __half* xa, __half* xout,
    __half* hsm, __half* Msm, float* alj,
    const unsigned char* srcS, const int* off,
    int t, int lane, int w)
{
    const int r = lane >> 2, q = lane & 3;

    // ---- GEMM: D[nt] = x(16xK) @ W(Kx8), 16 n-tiles (cols 128w..) ----
    float4 D[16];
    #pragma unroll
    for (int nt = 0; nt < 16; nt++) D[nt] = make_float4(0.f, 0.f, 0.f, 0.f);

    const uint xaddr = smaddr(xa) + ((lane & 15) * XSTH + (lane >> 4) * 8) * 2;
    const uint2* wp = Wh + (w*16)*32 + lane;
    #pragma unroll 2
    for (int kt = 0; kt < KT; kt++) {
        uint a0, a1, a2, a3;
        ldsm4(a0, a1, a2, a3, xaddr + kt*32);
        #pragma unroll
        for (int nt = 0; nt < 16; nt++) {
            uint2 b = wp[kt*1024 + nt*32];
            mma_f16(D[nt], a0, a1, a2, a3, b.x, b.y);
        }
    }

    // ---- attention logits (heads 2w, 2w+1) from D fragments ----
    {
        float ss[2][2] = {{0.f,0.f},{0.f,0.f}};   // [head-sel][row-sel]
        float sd[2][2] = {{0.f,0.f},{0.f,0.f}};
        const float4* afp = af + (w*16)*32 + lane;
        #pragma unroll
        for (int nt = 0; nt < 16; nt++) {
            float4 A = afp[nt*32];
            int hs = nt >> 3;
            ss[hs][0] = fmaf(D[nt].x, A.x, fmaf(D[nt].y, A.y, ss[hs][0]));
            ss[hs][1] = fmaf(D[nt].z, A.x, fmaf(D[nt].w, A.y, ss[hs][1]));
            sd[hs][0] = fmaf(D[nt].x, A.z, fmaf(D[nt].y, A.w, sd[hs][0]));
            sd[hs][1] = fmaf(D[nt].z, A.z, fmaf(D[nt].w, A.w, sd[hs][1]));
        }
        #pragma unroll
        for (int hs = 0; hs < 2; hs++)
            #pragma unroll
            for (int rs = 0; rs < 2; rs++) {
                #pragma unroll
                for (int o = 1; o < 4; o <<= 1) {
                    ss[hs][rs] += __shfl_xor_sync(0xffffffffu, ss[hs][rs], o);
                    sd[hs][rs] += __shfl_xor_sync(0xffffffffu, sd[hs][rs], o);
                }
            }
        if (q == 0) {
            #pragma unroll
            for (int hs = 0; hs < 2; hs++) {
                int h = 2*w + hs;
                alj[r*8 + h]     = ss[hs][0];
                alj[r*8 + 4 + h] = sd[hs][0];
                if (r < 6) {
                    alj[(r+8)*8 + h]     = ss[hs][1];
                    alj[(r+8)*8 + 4 + h] = sd[hs][1];
                }
            }
        }
    }
    __syncwarp();

    // ---- M-build fp16, one row per lane: head hs=lane>>4, d=lane&15 ----
    {
        int hs = lane >> 4, d = lane & 15;
        int hh = 2*w + hs;
        __half2* Mr = (__half2*)(Msm + hh*16*MST + d*MST);
        if (d < NN) {
            float md[NN];
            #pragma unroll
            for (int s = 0; s < NN; s++) md[s] = 0.f;
            float ad = alj[d*8 + 4 + hh];
            float dn = 0.f;
            int e1 = off[d+1];
            for (int e = off[d]; e < e1; e++) {
                int s = srcS[e];
                float v = alj[s*8 + hh] + ad;
                v = (v > 0.f) ? v : NEG * v;
                float ex = __expf(v);
                md[s] += ex;
                dn += ex;
            }
            float inv = __fdividef(1.f, dn);
            #pragma unroll
            for (int j = 0; j < 7; j++)
                Mr[j] = __halves2half2(__float2half_rn(md[2*j]*inv),
                                       __float2half_rn(md[2*j+1]*inv));
            Mr[7] = __halves2half2(__float2half_rn(0.f), __float2half_rn(0.f));
        } else {
            #pragma unroll
            for (int j = 0; j < 8; j++)
                Mr[j] = __halves2half2(__float2half_rn(0.f), __float2half_rn(0.f));
        }
    }

    // ---- stage h (fp16) into this warp's column slice of hsm ----
    {
        #pragma unroll
        for (int nt = 0; nt < 16; nt++) {
            int c0 = w*128 + nt*8 + 2*q;
            *(__half2*)&hsm[r*HST + c0] =
                __halves2half2(__float2half_rn(D[nt].x), __float2half_rn(D[nt].y));
            *(__half2*)&hsm[(r+8)*HST + c0] =
                __halves2half2(__float2half_rn(D[nt].z), __float2half_rn(D[nt].w));
        }
    }
    __syncwarp();

    // ---- aggregation via mma: D2 = M_h(16x16) @ h(16x128), head by n-tile ----
    float4 D2[16];
    {
        uint ma0, ma1, ma2, ma3, mb0, mb1, mb2, mb3;
        uint mbase = smaddr(Msm) + ((lane & 15)*MST + (lane >> 4)*8) * 2;
        ldsm4(ma0, ma1, ma2, ma3, mbase + (2*w)*16*MST*2);
        ldsm4(mb0, mb1, mb2, mb3, mbase + (2*w+1)*16*MST*2);
        const uint hrow = ((lane & 7) + ((lane >> 3) & 1) * 8) * HST;
        #pragma unroll
        for (int p2 = 0; p2 < 8; p2++) {
            uint b00, b01, b10, b11;
            uint haddr = smaddr(hsm) + (hrow + w*128 + p2*16 + (lane >> 4)*8) * 2;
            ldsm4t(b00, b01, b10, b11, haddr);
            float4 da = make_float4(0.f,0.f,0.f,0.f);
            float4 db = make_float4(0.f,0.f,0.f,0.f);
            if (p2 < 4) {
                mma_f16(da, ma0, ma1, ma2, ma3, b00, b01);
                mma_f16(db, ma0, ma1, ma2, ma3, b10, b11);
            } else {
                mma_f16(da, mb0, mb1, mb2, mb3, b00, b01);
                mma_f16(db, mb0, mb1, mb2, mb3, b10, b11);
            }
            D2[2*p2]   = da;
            D2[2*p2+1] = db;
        }
    }

    // ---- head-pair sum, store f32 into own (now dead) hsm slice ----
    {
        float* hf = (float*)hsm;
        #pragma unroll
        for (int k = 0; k < 8; k++) {
            float4 a = D2[k], b = D2[k+8];
            int c0 = ((k >> 1)*16 + (k & 1)*8 + 2*q) + w*64;
            *(float2*)&hf[r*132 + c0]     = make_float2(a.x + b.x, a.y + b.y);
            *(float2*)&hf[(r+8)*132 + c0] = make_float2(a.z + b.z, a.w + b.w);
        }
    }
    __syncthreads();   // both warps' pair-sums ready; all xa reads done

    // ---- head mean + bias (+relu) -> xout fp16; pad rows zeroed ----
    {
        const float* hf = (const float*)hsm;
        for (int i = t; i < NN*NC; i += 64) {
            int n = i >> 6, c = i & 63;
            float v = 0.25f * (hf[n*132 + c] + hf[n*132 + 64 + c]) + bias[c];
            if (RELU) v = fmaxf(v, 0.f);
            xout[n*XSTH + c] = __float2half_rn(v);
        }
        for (int i = t; i < 2*XSTH; i += 64) xout[NN*XSTH + i] = __float2half_rn(0.f);
    }
    __syncthreads();   // xout ready
}

__global__ void __launch_bounds__(64, 8)
gat_kernel(const float* __restrict__ feature, const int* __restrict__ eraw,
           const float* __restrict__ b1v, const float* __restrict__ b2v,
           float* __restrict__ out, int E)
{
    __shared__ __align__(16) __half xh[16*XSTH];
    __shared__ __align__(16) __half x2h[16*XSTH];
    __shared__ __align__(16) __half hsm[16*HST];
    __shared__ __align__(16) __half Msm[4*16*MST];
    __shared__ float alj[NN*8];
    __shared__ unsigned char srcS[MAXE];
    __shared__ int cnt[NN], off[NN+1];
    __shared__ float red[2];

    const int g = blockIdx.x;
    const int t = threadIdx.x;
    const int lane = t & 31, w = t >> 5;
    const int NE = E + NN;
    const int is64 = g_is64;

    if (w == 0) {
        // ---- warp 0: counting sort of edges by dst (self-loops appended) ----
        if (lane < NN) cnt[lane] = 0;
        __syncwarp();
        for (int e = lane; e < NE; e += 32) {
            int d;
            if (e < E) {
                size_t base = ((size_t)g * E + e) * 2;
                d = is64 ? (int)((const long long*)eraw)[base + 1] : eraw[base + 1];
            } else d = e - E;
            atomicAdd(&cnt[d], 1);
        }
        __syncwarp();
        if (lane == 0) {
            int s = 0;
            #pragma unroll
            for (int i = 0; i < NN; i++) { off[i] = s; s += cnt[i]; cnt[i] = off[i]; }
            off[NN] = s;
        }
        __syncwarp();
        for (int e = lane; e < NE; e += 32) {
            int s, d;
            if (e < E) {
                size_t base = ((size_t)g * E + e) * 2;
                if (is64) { const long long* p = (const long long*)eraw;
                            s = (int)p[base]; d = (int)p[base + 1]; }
                else      { s = eraw[base];   d = eraw[base + 1]; }
            } else { s = d = e - E; }
            int pos = atomicAdd(&cnt[d], 1);
            srcS[pos] = (unsigned char)s;
        }
    } else {
        // ---- warp 1: load features -> fp16 xh [16][XSTH]; zero pad rows ----
        const float4* xg = (const float4*)(feature + (size_t)g * NN * FIN);
        for (int i = lane; i < NN*32; i += 32) {
            int n = i >> 5, k4 = i & 31;
            float4 v = xg[i];
            __half2 lo = __halves2half2(__float2half_rn(v.x), __float2half_rn(v.y));
            __half2 hi = __halves2half2(__float2half_rn(v.z), __float2half_rn(v.w));
            *(uint2*)&xh[n*XSTH + k4*4] = make_uint2(*(uint*)&lo, *(uint*)&hi);
        }
        for (int i = lane; i < 2*XSTH; i += 32) xh[NN*XSTH + i] = __float2half_rn(0.f);
    }
    __syncthreads();

    gat_layer<8, true >(g_W1h, g_af1, b1v, xh,  x2h, hsm, Msm, alj,
                        srcS, off, t, lane, w);
    gat_layer<4, false>(g_W2h, g_af2, b2v, x2h, x2h, hsm, Msm, alj,
                        srcS, off, t, lane, w);

    // ---- fused head: sigmoid(flat . w_fused + b_fused) ----
    float p = 0.f;
    for (int i = t; i < NN*NC; i += 64) {
        int n = i >> 6, c = i & 63;
        p = fmaf(__half2float(x2h[n*XSTH + c]), g_wfused[i], p);
    }
    #pragma unroll
    for (int o = 16; o; o >>= 1) p += __shfl_xor_sync(0xffffffffu, p, o);
    if (lane == 0) red[w] = p;
    __syncthreads();
    if (t == 0) {
        float s = g_bfused + red[0] + red[1];
        out[g] = 1.f / (1.f + __expf(-s));
    }
}

extern "C" void kernel_launch(void* const* d_in, const int* in_sizes, int n_in,
                              void* d_out, int out_size)
{
    const float* feature = (const float*)d_in[0];
    const int*   edges   = (const int*)  d_in[1];
    const float* W1   = (const float*)d_in[2];
    const float* as1  = (const float*)d_in[3];
    const float* ad1  = (const float*)d_in[4];
    const float* b1   = (const float*)d_in[5];
    const float* W2   = (const float*)d_in[6];
    const float* as2  = (const float*)d_in[7];
    const float* ad2  = (const float*)d_in[8];
    const float* b2   = (const float*)d_in[9];
    const float* Wlin = (const float*)d_in[10];
    const float* blin = (const float*)d_in[11];
    const float* Wpred= (const float*)d_in[12];
    const float* bpred= (const float*)d_in[13];

    int B = in_sizes[0] / (NN * FIN);       // 16384
    int E = in_sizes[1] / (2 * B);          // 182

    prep_kernel<<<48, 256>>>(W1, as1, ad1, W2, as2, ad2,
                             Wlin, blin, Wpred, bpred, edges);
    gat_kernel<<<B, 64>>>(feature, edges, b1, b2, (float*)d_out, E);
}

// round 16
// speedup vs baseline: 1.4587x; 1.1459x over previous
#include <cuda_runtime.h>
#include <cuda_fp16.h>

#define NN 14      // nodes per graph
#define NH 4       // heads
#define NC 64      // per-head channels
#define NO 256     // NH*NC
#define FIN 128
#define NEG 0.2f
#define XSTH 136   // xh/x2h row stride (halves)
#define HST 264    // hsm row stride (halves); float view stride 132
#define MST 24     // Msm row stride (halves)

typedef unsigned int uint;

__device__ __forceinline__ uint smaddr(const void* p) {
    return (uint)__cvta_generic_to_shared(p);
}
__device__ __forceinline__ void ldsm4(uint& r0, uint& r1, uint& r2, uint& r3, uint a) {
    asm volatile("ldmatrix.sync.aligned.m8n8.x4.shared.b16 {%0,%1,%2,%3},[%4];"
        : "=r"(r0), "=r"(r1), "=r"(r2), "=r"(r3) : "r"(a));
}
__device__ __forceinline__ void ldsm4t(uint& r0, uint& r1, uint& r2, uint& r3, uint a) {
    asm volatile("ldmatrix.sync.aligned.m8n8.x4.trans.shared.b16 {%0,%1,%2,%3},[%4];"
        : "=r"(r0), "=r"(r1), "=r"(r2), "=r"(r3) : "r"(a));
}
// D(16x8,f32) += A(16x16,f16) @ B(16x8,f16)
__device__ __forceinline__ void mma_f16(float4& d, uint a0, uint a1, uint a2, uint a3,
                                        uint b0, uint b1) {
    asm("mma.sync.aligned.m16n8k16.row.col.f32.f16.f16.f32 "
        "{%0,%1,%2,%3}, {%4,%5,%6,%7}, {%8,%9}, {%0,%1,%2,%3};"
        : "+f"(d.x), "+f"(d.y), "+f"(d.z), "+f"(d.w)
        : "r"(a0), "r"(a1), "r"(a2), "r"(a3), "r"(b0), "r"(b1));
}

// ---- precomputed weights ----
// uint4-packed pairs of B fragments: g_Wq[(kt*16 + ntp)*32 + lane] holds
// (b0,b1) of n-tile 2ntp and (b0,b1) of n-tile 2ntp+1.
__device__ uint4 g_W1q[8 * 16 * 32];
__device__ uint4 g_W2q[4 * 16 * 32];
// folded attention-logit tile (j=0..3: W@a_src head j; j=4..7: W@a_dst head j-4)
__device__ uint2 g_Wa1[8 * 32];
__device__ uint2 g_Wa2[4 * 32];
__device__ float  g_wfused[NN * NC];   // W_lin @ W_pred
__device__ float  g_bfused;
__device__ int    g_is64;

__device__ __forceinline__ float waSD_val(const float* W, const float* as_,
                                          const float* ad_, int j, int k) {
    int hh = j & 3;
    const float* av = (j < 4) ? as_ : ad_;
    float s = 0.f;
    for (int c = 0; c < NC; c++)
        s = fmaf(W[k*NO + hh*NC + c], av[hh*NC + c], s);
    return s;
}

__global__ void prep_kernel(const float* __restrict__ W1, const float* __restrict__ as1,
                            const float* __restrict__ ad1,
                            const float* __restrict__ W2, const float* __restrict__ as2,
                            const float* __restrict__ ad2,
                            const float* __restrict__ Wlin, const float* __restrict__ blin,
                            const float* __restrict__ Wpred, const float* __restrict__ bpred,
                            const int* __restrict__ edges)
{
    int tid = blockIdx.x * blockDim.x + threadIdx.x;
    int nt  = gridDim.x * blockDim.x;

    for (int i = tid; i < 8*16*32; i += nt) {
        int kt = i >> 9, r = i & 511, ntp = r >> 5, lane = r & 31;
        int q = lane & 3, rr = lane >> 2;
        int k0 = kt*16 + 2*q;
        int n0 = (2*ntp)*8 + rr, n1 = (2*ntp+1)*8 + rr;
        __half2 a0 = __floats2half2_rn(W1[k0*NO + n0],     W1[(k0+1)*NO + n0]);
        __half2 a1 = __floats2half2_rn(W1[(k0+8)*NO + n0], W1[(k0+9)*NO + n0]);
        __half2 c0 = __floats2half2_rn(W1[k0*NO + n1],     W1[(k0+1)*NO + n1]);
        __half2 c1 = __floats2half2_rn(W1[(k0+8)*NO + n1], W1[(k0+9)*NO + n1]);
        g_W1q[i] = make_uint4(*(uint*)&a0, *(uint*)&a1, *(uint*)&c0, *(uint*)&c1);
    }
    for (int i = tid; i < 4*16*32; i += nt) {
        int kt = i >> 9, r = i & 511, ntp = r >> 5, lane = r & 31;
        int q = lane & 3, rr = lane >> 2;
        int k0 = kt*16 + 2*q;
        int n0 = (2*ntp)*8 + rr, n1 = (2*ntp+1)*8 + rr;
        __half2 a0 = __floats2half2_rn(W2[k0*NO + n0],     W2[(k0+1)*NO + n0]);
        __half2 a1 = __floats2half2_rn(W2[(k0+8)*NO + n0], W2[(k0+9)*NO + n0]);
        __half2 c0 = __floats2half2_rn(W2[k0*NO + n1],     W2[(k0+1)*NO + n1]);
        __half2 c1 = __floats2half2_rn(W2[(k0+8)*NO + n1], W2[(k0+9)*NO + n1]);
        g_W2q[i] = make_uint4(*(uint*)&a0, *(uint*)&a1, *(uint*)&c0, *(uint*)&c1);
    }
    for (int i = tid; i < 8*32; i += nt) {
        int kt = i >> 5, lane = i & 31;
        int q = lane & 3, j = lane >> 2;
        int k0 = kt*16 + 2*q;
        __half2 b0 = __floats2half2_rn(waSD_val(W1, as1, ad1, j, k0),
                                       waSD_val(W1, as1, ad1, j, k0+1));
        __half2 b1 = __floats2half2_rn(waSD_val(W1, as1, ad1, j, k0+8),
                                       waSD_val(W1, as1, ad1, j, k0+9));
        g_Wa1[i] = make_uint2(*(uint*)&b0, *(uint*)&b1);
    }
    for (int i = tid; i < 4*32; i += nt) {
        int kt = i >> 5, lane = i & 31;
        int q = lane & 3, j = lane >> 2;
        int k0 = kt*16 + 2*q;
        __half2 b0 = __floats2half2_rn(waSD_val(W2, as2, ad2, j, k0),
                                       waSD_val(W2, as2, ad2, j, k0+1));
        __half2 b1 = __floats2half2_rn(waSD_val(W2, as2, ad2, j, k0+8),
                                       waSD_val(W2, as2, ad2, j, k0+9));
        g_Wa2[i] = make_uint2(*(uint*)&b0, *(uint*)&b1);
    }
    for (int i = tid; i < NN * NC; i += nt) {
        float s = 0.f;
        #pragma unroll
        for (int j = 0; j < NC/2; j++) s = fmaf(Wlin[i*(NC/2) + j], Wpred[j], s);
        g_wfused[i] = s;
    }
    if (tid == 0) {
        float s = bpred[0];
        #pragma unroll
        for (int j = 0; j < NC/2; j++) s = fmaf(blin[j], Wpred[j], s);
        g_bfused = s;
        int any = 0;
        #pragma unroll
        for (int k = 1; k < 256; k += 2) any |= edges[k];
        g_is64 = (any == 0) ? 1 : 0;
    }
}

// One GAT layer; 2-warp CTA, warp w owns cols 128w.. (heads 2w, 2w+1).
// Warp 0 additionally computes the folded attention-logit tile.
// Dense attention built from count matrix cntf (duplicate edges = counts).
template<int KT, bool RELU>
__device__ __forceinline__ void gat_layer(
    const uint4* __restrict__ Wq, const uint2* __restrict__ Wa,
    const float* __restrict__ bias,
    const __half* xa, __half* xout,
    __half* hsm, __half* Msm, float* alj, const float* cntf,
    int t, int lane, int w)
{
    const int r = lane >> 2, q = lane & 3;

    // ---- GEMM: D[nt] = x(16xK) @ W(Kx8), 16 n-tiles + (w0) alj tile ----
    float4 D[16];
    #pragma unroll
    for (int nt = 0; nt < 16; nt++) D[nt] = make_float4(0.f, 0.f, 0.f, 0.f);
    float4 Dal = make_float4(0.f, 0.f, 0.f, 0.f);

    const uint xaddr = smaddr(xa) + ((lane & 15) * XSTH + (lane >> 4) * 8) * 2;
    const uint4* wp = Wq + (w*8)*32 + lane;
    #pragma unroll 2
    for (int kt = 0; kt < KT; kt++) {
        uint a0, a1, a2, a3;
        ldsm4(a0, a1, a2, a3, xaddr + kt*32);
        #pragma unroll
        for (int ntp = 0; ntp < 8; ntp++) {
            uint4 b = wp[kt*512 + ntp*32];
            mma_f16(D[2*ntp],   a0, a1, a2, a3, b.x, b.y);
            mma_f16(D[2*ntp+1], a0, a1, a2, a3, b.z, b.w);
        }
        if (w == 0) {
            uint2 ba = Wa[kt*32 + lane];
            mma_f16(Dal, a0, a1, a2, a3, ba.x, ba.y);
        }
    }

    // ---- warp0: store alj fragments directly (alj[n][j], j=src0..3,dst0..3) ----
    if (w == 0) {
        *(float2*)&alj[r*8 + 2*q] = make_float2(Dal.x, Dal.y);
        if (r < 6)
            *(float2*)&alj[(r+8)*8 + 2*q] = make_float2(Dal.z, Dal.w);
    }

    // ---- stage h (fp16) into this warp's column slice of hsm ----
    {
        #pragma unroll
        for (int nt = 0; nt < 16; nt++) {
            int c0 = w*128 + nt*8 + 2*q;
            *(__half2*)&hsm[r*HST + c0]     = __floats2half2_rn(D[nt].x, D[nt].y);
            *(__half2*)&hsm[(r+8)*HST + c0] = __floats2half2_rn(D[nt].z, D[nt].w);
        }
    }
    __syncthreads();   // alj visible to both warps; staging done

    // ---- dense M-build (fp16 fragment layout), one row per lane ----
    {
        int hs = lane >> 4, d = lane & 15;
        int hh = 2*w + hs;
        __half2* Mr = (__half2*)(Msm + hh*16*MST + d*MST);
        if (d < NN) {
            float md[NN];
            float ad = alj[d*8 + 4 + hh];
            float dn = 0.f;
            #pragma unroll
            for (int s = 0; s < NN; s++) {
                float v = alj[s*8 + hh] + ad;
                v = (v > 0.f) ? v : NEG * v;
                float ex = __expf(v) * cntf[d*NN + s];
                md[s] = ex;
                dn += ex;
            }
            float inv = __fdividef(1.f, dn);
            #pragma unroll
            for (int j = 0; j < 7; j++)
                Mr[j] = __floats2half2_rn(md[2*j]*inv, md[2*j+1]*inv);
            Mr[7] = __floats2half2_rn(0.f, 0.f);
        } else {
            #pragma unroll
            for (int j = 0; j < 8; j++)
                Mr[j] = __floats2half2_rn(0.f, 0.f);
        }
    }
    __syncwarp();

    // ---- aggregation via mma: D2 = M_h(16x16) @ h(16x128), head by n-tile ----
    float4 D2[16];
    {
        uint ma0, ma1, ma2, ma3, mb0, mb1, mb2, mb3;
        uint mbase = smaddr(Msm) + ((lane & 15)*MST + (lane >> 4)*8) * 2;
        ldsm4(ma0, ma1, ma2, ma3, mbase + (2*w)*16*MST*2);
        ldsm4(mb0, mb1, mb2, mb3, mbase + (2*w+1)*16*MST*2);
        const uint hrow = ((lane & 7) + ((lane >> 3) & 1) * 8) * HST;
        #pragma unroll
        for (int p2 = 0; p2 < 8; p2++) {
            uint b00, b01, b10, b11;
            uint haddr = smaddr(hsm) + (hrow + w*128 + p2*16 + (lane >> 4)*8) * 2;
            ldsm4t(b00, b01, b10, b11, haddr);
            float4 da = make_float4(0.f,0.f,0.f,0.f);
            float4 db = make_float4(0.f,0.f,0.f,0.f);
            if (p2 < 4) {
                mma_f16(da, ma0, ma1, ma2, ma3, b00, b01);
                mma_f16(db, ma0, ma1, ma2, ma3, b10, b11);
            } else {
                mma_f16(da, mb0, mb1, mb2, mb3, b00, b01);
                mma_f16(db, mb0, mb1, mb2, mb3, b10, b11);
            }
            D2[2*p2]   = da;
            D2[2*p2+1] = db;
        }
    }

    // ---- head-pair sum, store f32 into own (now dead) hsm slice ----
    {
        float* hf = (float*)hsm;
        #pragma unroll
        for (int k = 0; k < 8; k++) {
            float4 a = D2[k], b = D2[k+8];
            int c0 = ((k >> 1)*16 + (k & 1)*8 + 2*q) + w*64;
            *(float2*)&hf[r*132 + c0]     = make_float2(a.x + b.x, a.y + b.y);
            *(float2*)&hf[(r+8)*132 + c0] = make_float2(a.z + b.z, a.w + b.w);
        }
    }
    __syncthreads();   // both warps' pair-sums ready; all xa reads done

    // ---- head mean + bias (+relu) -> xout fp16; pad rows zeroed ----
    {
        const float* hf = (const float*)hsm;
        for (int i = t; i < NN*NC; i += 64) {
            int n = i >> 6, c = i & 63;
            float v = 0.25f * (hf[n*132 + c] + hf[n*132 + 64 + c]) + bias[c];
            if (RELU) v = fmaxf(v, 0.f);
            xout[n*XSTH + c] = __float2half_rn(v);
        }
        for (int i = t; i < 2*XSTH; i += 64) xout[NN*XSTH + i] = __float2half_rn(0.f);
    }
    __syncthreads();   // xout ready
}

__global__ void __launch_bounds__(64, 8)
gat_kernel(const float* __restrict__ feature, const int* __restrict__ eraw,
           const float* __restrict__ b1v, const float* __restrict__ b2v,
           float* __restrict__ out, int E)
{
    __shared__ __align__(16) __half xh[16*XSTH];
    __shared__ __align__(16) __half x2h[16*XSTH];
    __shared__ __align__(16) __half hsm[16*HST];
    __shared__ __align__(16) __half Msm[4*16*MST];
    __shared__ __align__(8)  float alj[NN*8];
    __shared__ float cntf[NN*NN];
    __shared__ float red[2];

    const int g = blockIdx.x;
    const int t = threadIdx.x;
    const int lane = t & 31, w = t >> 5;
    const int is64 = g_is64;

    if (w == 0) {
        // ---- warp 0: dense edge-count matrix (diag init 1 for self-loops) ----
        for (int i = lane; i < NN*NN; i += 32)
            cntf[i] = (i % (NN+1) == 0) ? 1.f : 0.f;
        __syncwarp();
        for (int e = lane; e < E; e += 32) {
            size_t base = ((size_t)g * E + e) * 2;
            int s, d;
            if (is64) { const long long* p = (const long long*)eraw;
                        s = (int)p[base]; d = (int)p[base + 1]; }
            else      { s = eraw[base];   d = eraw[base + 1]; }
            atomicAdd(&cntf[d*NN + s], 1.f);
        }
    } else {
        // ---- warp 1: load features -> fp16 xh [16][XSTH]; zero pad rows ----
        const float4* xg = (const float4*)(feature + (size_t)g * NN * FIN);
        for (int i = lane; i < NN*32; i += 32) {
            int n = i >> 5, k4 = i & 31;
            float4 v = xg[i];
            __half2 lo = __floats2half2_rn(v.x, v.y);
            __half2 hi = __floats2half2_rn(v.z, v.w);
            *(uint2*)&xh[n*XSTH + k4*4] = make_uint2(*(uint*)&lo, *(uint*)&hi);
        }
        for (int i = lane; i < 2*XSTH; i += 32) xh[NN*XSTH + i] = __float2half_rn(0.f);
    }
    __syncthreads();

    gat_layer<8, true >(g_W1q, g_Wa1, b1v, xh,  x2h, hsm, Msm, alj, cntf,
                        t, lane, w);
    gat_layer<4, false>(g_W2q, g_Wa2, b2v, x2h, x2h, hsm, Msm, alj, cntf,
                        t, lane, w);

    // ---- fused head: sigmoid(flat . w_fused + b_fused) ----
    float p = 0.f;
    for (int i = t; i < NN*NC; i += 64) {
        int n = i >> 6, c = i & 63;
        p = fmaf(__half2float(x2h[n*XSTH + c]), g_wfused[i], p);
    }
    #pragma unroll
    for (int o = 16; o; o >>= 1) p += __shfl_xor_sync(0xffffffffu, p, o);
    if (lane == 0) red[w] = p;
    __syncthreads();
    if (t == 0) {
        float s = g_bfused + red[0] + red[1];
        out[g] = 1.f / (1.f + __expf(-s));
    }
}

extern "C" void kernel_launch(void* const* d_in, const int* in_sizes, int n_in,
                              void* d_out, int out_size)
{
    const float* feature = (const float*)d_in[0];
    const int*   edges   = (const int*)  d_in[1];
    const float* W1   = (const float*)d_in[2];
    const float* as1  = (const float*)d_in[3];
    const float* ad1  = (const float*)d_in[4];
    const float* b1   = (const float*)d_in[5];
    const float* W2   = (const float*)d_in[6];
    const float* as2  = (const float*)d_in[7];
    const float* ad2  = (const float*)d_in[8];
    const float* b2   = (const float*)d_in[9];
    const float* Wlin = (const float*)d_in[10];
    const float* blin = (const float*)d_in[11];
    const float* Wpred= (const float*)d_in[12];
    const float* bpred= (const float*)d_in[13];

    int B = in_sizes[0] / (NN * FIN);       // 16384
    int E = in_sizes[1] / (2 * B);          // 182

    prep_kernel<<<48, 256>>>(W1, as1, ad1, W2, as2, ad2,
                             Wlin, blin, Wpred, bpred, edges);
    gat_kernel<<<B, 64>>>(feature, edges, b1, b2, (float*)d_out, E);
}

// round 17
// speedup vs baseline: 1.5610x; 1.0702x over previous
#include <cuda_runtime.h>
#include <cuda_fp16.h>

#define NN 14      // nodes per graph
#define NH 4       // heads
#define NC 64      // per-head channels
#define NO 256     // NH*NC
#define FIN 128
#define NEG 0.2f
#define XSTH 136   // xh/x2h row stride (halves)
#define HST 264    // hsm row stride (halves); float view stride 132
#define MST 24     // Msm row stride (halves)

#define NWORK 5            // workers (graphs in flight) per CTA
#define NT (NWORK*64)      // 320 threads
#define GRID 148           // persistent CTAs (1 per SM)

// dynamic smem layout (bytes)
#define OFF_W2  65536
#define OFF_WA1 98304
#define OFF_WA2 100352
#define OFF_WK  101376
#define WKSZ    21504
#define SMEM_TOTAL (OFF_WK + NWORK*WKSZ)   // 208896

typedef unsigned int uint;

__device__ __forceinline__ uint smaddr(const void* p) {
    return (uint)__cvta_generic_to_shared(p);
}
__device__ __forceinline__ void ldsm4(uint& r0, uint& r1, uint& r2, uint& r3, uint a) {
    asm volatile("ldmatrix.sync.aligned.m8n8.x4.shared.b16 {%0,%1,%2,%3},[%4];"
        : "=r"(r0), "=r"(r1), "=r"(r2), "=r"(r3) : "r"(a));
}
__device__ __forceinline__ void ldsm4t(uint& r0, uint& r1, uint& r2, uint& r3, uint a) {
    asm volatile("ldmatrix.sync.aligned.m8n8.x4.trans.shared.b16 {%0,%1,%2,%3},[%4];"
        : "=r"(r0), "=r"(r1), "=r"(r2), "=r"(r3) : "r"(a));
}
__device__ __forceinline__ void mma_f16(float4& d, uint a0, uint a1, uint a2, uint a3,
                                        uint b0, uint b1) {
    asm("mma.sync.aligned.m16n8k16.row.col.f32.f16.f16.f32 "
        "{%0,%1,%2,%3}, {%4,%5,%6,%7}, {%8,%9}, {%0,%1,%2,%3};"
        : "+f"(d.x), "+f"(d.y), "+f"(d.z), "+f"(d.w)
        : "r"(a0), "r"(a1), "r"(a2), "r"(a3), "r"(b0), "r"(b1));
}
__device__ __forceinline__ void barp(int id) {
    asm volatile("bar.sync %0, %1;" :: "r"(id), "r"(64) : "memory");
}

// ---- precomputed weights (global; copied to smem by the persistent kernel) ----
__device__ uint4 g_W1q[8 * 16 * 32];
__device__ uint4 g_W2q[4 * 16 * 32];
__device__ uint2 g_Wa1[8 * 32];
__device__ uint2 g_Wa2[4 * 32];
__device__ float  g_wfused[NN * NC];   // W_lin @ W_pred
__device__ float  g_bfused;
__device__ int    g_is64;

__device__ __forceinline__ float waSD_val(const float* W, const float* as_,
                                          const float* ad_, int j, int k) {
    int hh = j & 3;
    const float* av = (j < 4) ? as_ : ad_;
    float s = 0.f;
    for (int c = 0; c < NC; c++)
        s = fmaf(W[k*NO + hh*NC + c], av[hh*NC + c], s);
    return s;
}

__global__ void prep_kernel(const float* __restrict__ W1, const float* __restrict__ as1,
                            const float* __restrict__ ad1,
                            const float* __restrict__ W2, const float* __restrict__ as2,
                            const float* __restrict__ ad2,
                            const float* __restrict__ Wlin, const float* __restrict__ blin,
                            const float* __restrict__ Wpred, const float* __restrict__ bpred,
                            const int* __restrict__ edges)
{
    int tid = blockIdx.x * blockDim.x + threadIdx.x;
    int nt  = gridDim.x * blockDim.x;

    for (int i = tid; i < 8*16*32; i += nt) {
        int kt = i >> 9, r = i & 511, ntp = r >> 5, lane = r & 31;
        int q = lane & 3, rr = lane >> 2;
        int k0 = kt*16 + 2*q;
        int n0 = (2*ntp)*8 + rr, n1 = (2*ntp+1)*8 + rr;
        __half2 a0 = __floats2half2_rn(W1[k0*NO + n0],     W1[(k0+1)*NO + n0]);
        __half2 a1 = __floats2half2_rn(W1[(k0+8)*NO + n0], W1[(k0+9)*NO + n0]);
        __half2 c0 = __floats2half2_rn(W1[k0*NO + n1],     W1[(k0+1)*NO + n1]);
        __half2 c1 = __floats2half2_rn(W1[(k0+8)*NO + n1], W1[(k0+9)*NO + n1]);
        g_W1q[i] = make_uint4(*(uint*)&a0, *(uint*)&a1, *(uint*)&c0, *(uint*)&c1);
    }
    for (int i = tid; i < 4*16*32; i += nt) {
        int kt = i >> 9, r = i & 511, ntp = r >> 5, lane = r & 31;
        int q = lane & 3, rr = lane >> 2;
        int k0 = kt*16 + 2*q;
        int n0 = (2*ntp)*8 + rr, n1 = (2*ntp+1)*8 + rr;
        __half2 a0 = __floats2half2_rn(W2[k0*NO + n0],     W2[(k0+1)*NO + n0]);
        __half2 a1 = __floats2half2_rn(W2[(k0+8)*NO + n0], W2[(k0+9)*NO + n0]);
        __half2 c0 = __floats2half2_rn(W2[k0*NO + n1],     W2[(k0+1)*NO + n1]);
        __half2 c1 = __floats2half2_rn(W2[(k0+8)*NO + n1], W2[(k0+9)*NO + n1]);
        g_W2q[i] = make_uint4(*(uint*)&a0, *(uint*)&a1, *(uint*)&c0, *(uint*)&c1);
    }
    for (int i = tid; i < 8*32; i += nt) {
        int kt = i >> 5, lane = i & 31;
        int q = lane & 3, j = lane >> 2;
        int k0 = kt*16 + 2*q;
        __half2 b0 = __floats2half2_rn(waSD_val(W1, as1, ad1, j, k0),
                                       waSD_val(W1, as1, ad1, j, k0+1));
        __half2 b1 = __floats2half2_rn(waSD_val(W1, as1, ad1, j, k0+8),
                                       waSD_val(W1, as1, ad1, j, k0+9));
        g_Wa1[i] = make_uint2(*(uint*)&b0, *(uint*)&b1);
    }
    for (int i = tid; i < 4*32; i += nt) {
        int kt = i >> 5, lane = i & 31;
        int q = lane & 3, j = lane >> 2;
        int k0 = kt*16 + 2*q;
        __half2 b0 = __floats2half2_rn(waSD_val(W2, as2, ad2, j, k0),
                                       waSD_val(W2, as2, ad2, j, k0+1));
        __half2 b1 = __floats2half2_rn(waSD_val(W2, as2, ad2, j, k0+8),
                                       waSD_val(W2, as2, ad2, j, k0+9));
        g_Wa2[i] = make_uint2(*(uint*)&b0, *(uint*)&b1);
    }
    for (int i = tid; i < NN * NC; i += nt) {
        float s = 0.f;
        #pragma unroll
        for (int j = 0; j < NC/2; j++) s = fmaf(Wlin[i*(NC/2) + j], Wpred[j], s);
        g_wfused[i] = s;
    }
    if (tid == 0) {
        float s = bpred[0];
        #pragma unroll
        for (int j = 0; j < NC/2; j++) s = fmaf(blin[j], Wpred[j], s);
        g_bfused = s;
        int any = 0;
        #pragma unroll
        for (int k = 1; k < 256; k += 2) any |= edges[k];
        g_is64 = (any == 0) ? 1 : 0;
    }
}

// One GAT layer for one worker (2 warps; warp w owns cols 128w.., heads 2w,2w+1).
// All weights come from shared memory. Named barrier barid scopes the worker.
template<int KT, bool RELU>
__device__ __forceinline__ void gat_layer(
    const uint4* Wq, const uint2* Wa, const float* __restrict__ bias,
    const __half* xa, __half* xout,
    __half* hsm, __half* Msm, float* alj, const float* cntf,
    int td, int lane, int w, int barid)
{
    const int r = lane >> 2, q = lane & 3;

    // ---- GEMM: D[nt] = x(16xK) @ W(Kx8), 16 n-tiles + (w0) alj tile ----
    float4 D[16];
    #pragma unroll
    for (int nt = 0; nt < 16; nt++) D[nt] = make_float4(0.f, 0.f, 0.f, 0.f);
    float4 Dal = make_float4(0.f, 0.f, 0.f, 0.f);

    const uint xaddr = smaddr(xa) + ((lane & 15) * XSTH + (lane >> 4) * 8) * 2;
    const uint4* wp = Wq + (w*8)*32 + lane;
    #pragma unroll 2
    for (int kt = 0; kt < KT; kt++) {
        uint a0, a1, a2, a3;
        ldsm4(a0, a1, a2, a3, xaddr + kt*32);
        #pragma unroll
        for (int ntp = 0; ntp < 8; ntp++) {
            uint4 b = wp[kt*512 + ntp*32];
            mma_f16(D[2*ntp],   a0, a1, a2, a3, b.x, b.y);
            mma_f16(D[2*ntp+1], a0, a1, a2, a3, b.z, b.w);
        }
        if (w == 0) {
            uint2 ba = Wa[kt*32 + lane];
            mma_f16(Dal, a0, a1, a2, a3, ba.x, ba.y);
        }
    }

    // ---- warp0: store alj fragments directly ----
    if (w == 0) {
        *(float2*)&alj[r*8 + 2*q] = make_float2(Dal.x, Dal.y);
        if (r < 6)
            *(float2*)&alj[(r+8)*8 + 2*q] = make_float2(Dal.z, Dal.w);
    }

    // ---- stage h (fp16) into this warp's column slice of hsm ----
    {
        #pragma unroll
        for (int nt = 0; nt < 16; nt++) {
            int c0 = w*128 + nt*8 + 2*q;
            *(__half2*)&hsm[r*HST + c0]     = __floats2half2_rn(D[nt].x, D[nt].y);
            *(__half2*)&hsm[(r+8)*HST + c0] = __floats2half2_rn(D[nt].z, D[nt].w);
        }
    }
    barp(barid);   // alj visible to both warps; staging done

    // ---- dense M-build (fp16 fragment layout), one row per lane ----
    {
        int hs = lane >> 4, d = lane & 15;
        int hh = 2*w + hs;
        __half2* Mr = (__half2*)(Msm + hh*16*MST + d*MST);
        if (d < NN) {
            float md[NN];
            float ad = alj[d*8 + 4 + hh];
            float dn = 0.f;
            #pragma unroll
            for (int s = 0; s < NN; s++) {
                float v = alj[s*8 + hh] + ad;
                v = (v > 0.f) ? v : NEG * v;
                float ex = __expf(v) * cntf[d*NN + s];
                md[s] = ex;
                dn += ex;
            }
            float inv = __fdividef(1.f, dn);
            #pragma unroll
            for (int j = 0; j < 7; j++)
                Mr[j] = __floats2half2_rn(md[2*j]*inv, md[2*j+1]*inv);
            Mr[7] = __floats2half2_rn(0.f, 0.f);
        } else {
            #pragma unroll
            for (int j = 0; j < 8; j++)
                Mr[j] = __floats2half2_rn(0.f, 0.f);
        }
    }
    __syncwarp();

    // ---- aggregation via mma: D2 = M_h(16x16) @ h(16x128) ----
    float4 D2[16];
    {
        uint ma0, ma1, ma2, ma3, mb0, mb1, mb2, mb3;
        uint mbase = smaddr(Msm) + ((lane & 15)*MST + (lane >> 4)*8) * 2;
        ldsm4(ma0, ma1, ma2, ma3, mbase + (2*w)*16*MST*2);
        ldsm4(mb0, mb1, mb2, mb3, mbase + (2*w+1)*16*MST*2);
        const uint hrow = ((lane & 7) + ((lane >> 3) & 1) * 8) * HST;
        #pragma unroll
        for (int p2 = 0; p2 < 8; p2++) {
            uint b00, b01, b10, b11;
            uint haddr = smaddr(hsm) + (hrow + w*128 + p2*16 + (lane >> 4)*8) * 2;
            ldsm4t(b00, b01, b10, b11, haddr);
            float4 da = make_float4(0.f,0.f,0.f,0.f);
            float4 db = make_float4(0.f,0.f,0.f,0.f);
            if (p2 < 4) {
                mma_f16(da, ma0, ma1, ma2, ma3, b00, b01);
                mma_f16(db, ma0, ma1, ma2, ma3, b10, b11);
            } else {
                mma_f16(da, mb0, mb1, mb2, mb3, b00, b01);
                mma_f16(db, mb0, mb1, mb2, mb3, b10, b11);
            }
            D2[2*p2]   = da;
            D2[2*p2+1] = db;
        }
    }

    // ---- head-pair sum, store f32 into own (now dead) hsm slice ----
    {
        float* hf = (float*)hsm;
        #pragma unroll
        for (int k = 0; k < 8; k++) {
            float4 a = D2[k], b = D2[k+8];
            int c0 = ((k >> 1)*16 + (k & 1)*8 + 2*q) + w*64;
            *(float2*)&hf[r*132 + c0]     = make_float2(a.x + b.x, a.y + b.y);
            *(float2*)&hf[(r+8)*132 + c0] = make_float2(a.z + b.z, a.w + b.w);
        }
    }
    barp(barid);   // both warps' pair-sums ready; all xa reads done

    // ---- head mean + bias (+relu) -> xout fp16; pad rows zeroed ----
    {
        const float* hf = (const float*)hsm;
        for (int i = td; i < NN*NC; i += 64) {
            int n = i >> 6, c = i & 63;
            float v = 0.25f * (hf[n*132 + c] + hf[n*132 + 64 + c]) + bias[c];
            if (RELU) v = fmaxf(v, 0.f);
            xout[n*XSTH + c] = __float2half_rn(v);
        }
        for (int i = td; i < 2*XSTH; i += 64) xout[NN*XSTH + i] = __float2half_rn(0.f);
    }
    barp(barid);   // xout ready
}

__global__ void __launch_bounds__(NT, 1)
gat_kernel(const float* __restrict__ feature, const int* __restrict__ eraw,
           const float* __restrict__ b1v, const float* __restrict__ b2v,
           float* __restrict__ out, int B, int E)
{
    extern __shared__ __align__(16) char smem[];
    uint4* sW1  = (uint4*)smem;
    uint4* sW2  = (uint4*)(smem + OFF_W2);
    uint2* sWa1 = (uint2*)(smem + OFF_WA1);
    uint2* sWa2 = (uint2*)(smem + OFF_WA2);

    const int t = threadIdx.x;
    const int worker = t >> 6;
    const int td = t & 63;
    const int lane = td & 31, w = td >> 5;
    const int barid = worker + 1;
    const int is64 = g_is64;

    // per-worker workspace
    char* wb = smem + OFF_WK + worker * WKSZ;
    __half* xh   = (__half*)wb;
    __half* x2h  = (__half*)(wb + 4352);
    __half* hsm  = (__half*)(wb + 8704);
    __half* Msm  = (__half*)(wb + 17152);
    float*  alj  = (float*)(wb + 20224);
    float*  cntf = (float*)(wb + 20672);
    float*  red  = (float*)(wb + 21456);

    // ---- one-time: copy all weights into smem ----
    for (int i = t; i < 8*16*32; i += NT) sW1[i] = g_W1q[i];
    for (int i = t; i < 4*16*32; i += NT) sW2[i] = g_W2q[i];
    for (int i = t; i < 8*32; i += NT)    sWa1[i] = g_Wa1[i];
    for (int i = t; i < 4*32; i += NT)    sWa2[i] = g_Wa2[i];
    __syncthreads();

    const int totalWorkers = gridDim.x * NWORK;
    for (int g = blockIdx.x * NWORK + worker; g < B; g += totalWorkers) {

        if (w == 0) {
            // ---- warp 0: dense edge-count matrix (diag init 1 = self-loops) ----
            for (int i = lane; i < NN*NN; i += 32)
                cntf[i] = (i % (NN+1) == 0) ? 1.f : 0.f;
            __syncwarp();
            for (int e = lane; e < E; e += 32) {
                size_t base = ((size_t)g * E + e) * 2;
                int s, d;
                if (is64) { const long long* p = (const long long*)eraw;
                            s = (int)p[base]; d = (int)p[base + 1]; }
                else      { s = eraw[base];   d = eraw[base + 1]; }
                atomicAdd(&cntf[d*NN + s], 1.f);
            }
        } else {
            // ---- warp 1: load features -> fp16 xh; zero pad rows ----
            const float4* xg = (const float4*)(feature + (size_t)g * NN * FIN);
            for (int i = lane; i < NN*32; i += 32) {
                int n = i >> 5, k4 = i & 31;
                float4 v = xg[i];
                __half2 lo = __floats2half2_rn(v.x, v.y);
                __half2 hi = __floats2half2_rn(v.z, v.w);
                *(uint2*)&xh[n*XSTH + k4*4] = make_uint2(*(uint*)&lo, *(uint*)&hi);
            }
            for (int i = lane; i < 2*XSTH; i += 32) xh[NN*XSTH + i] = __float2half_rn(0.f);
        }
        barp(barid);

        gat_layer<8, true >(sW1, sWa1, b1v, xh,  x2h, hsm, Msm, alj, cntf,
                            td, lane, w, barid);
        gat_layer<4, false>(sW2, sWa2, b2v, x2h, x2h, hsm, Msm, alj, cntf,
                            td, lane, w, barid);

        // ---- fused head: sigmoid(flat . w_fused + b_fused) ----
        float p = 0.f;
        for (int i = td; i < NN*NC; i += 64) {
            int n = i >> 6, c = i & 63;
            p = fmaf(__half2float(x2h[n*XSTH + c]), g_wfused[i], p);
        }
        #pragma unroll
        for (int o = 16; o; o >>= 1) p += __shfl_xor_sync(0xffffffffu, p, o);
        if (lane == 0) red[w] = p;
        barp(barid);
        if (td == 0) {
            float s = g_bfused + red[0] + red[1];
            out[g] = 1.f / (1.f + __expf(-s));
        }
        barp(barid);   // red reusable next iteration
    }
}

extern "C" void kernel_launch(void* const* d_in, const int* in_sizes, int n_in,
                              void* d_out, int out_size)
{
    const float* feature = (const float*)d_in[0];
    const int*   edges   = (const int*)  d_in[1];
    const float* W1   = (const float*)d_in[2];
    const float* as1  = (const float*)d_in[3];
    const float* ad1  = (const float*)d_in[4];
    const float* b1   = (const float*)d_in[5];
    const float* W2   = (const float*)d_in[6];
    const float* as2  = (const float*)d_in[7];
    const float* ad2  = (const float*)d_in[8];
    const float* b2   = (const float*)d_in[9];
    const float* Wlin = (const float*)d_in[10];
    const float* blin = (const float*)d_in[11];
    const float* Wpred= (const float*)d_in[12];
    const float* bpred= (const float*)d_in[13];

    int B = in_sizes[0] / (NN * FIN);       // 16384
    int E = in_sizes[1] / (2 * B);          // 182

    static int attr_done = 0;
    if (!attr_done) {
        cudaFuncSetAttribute(gat_kernel,
                             cudaFuncAttributeMaxDynamicSharedMemorySize, SMEM_TOTAL);
        attr_done = 1;
    }

    prep_kernel<<<48, 256>>>(W1, as1, ad1, W2, as2, ad2,
                             Wlin, blin, Wpred, bpred, edges);
    gat_kernel<<<GRID, NT, SMEM_TOTAL>>>(feature, edges, b1, b2,
                                         (float*)d_out, B, E);
}